// round 17
// baseline (speedup 1.0000x reference)
#include <cuda_runtime.h>

#define BB 512
#define TT 256

typedef unsigned long long u64;

// Inter-layer hidden sequences, batch-major [B, T, H]. Max H=256 -> 128 MB each.
__device__ float g_bufA[BB * TT * 256];
__device__ float g_bufB[BB * TT * 256];

__device__ __forceinline__ void ffma2(u64& d, u64 a, u64 b) {
    // packed fp32x2 fma: d.lo += a.lo*b.lo ; d.hi += a.hi*b.hi
    asm("fma.rn.f32x2 %0, %1, %2, %0;" : "+l"(d) : "l"(a), "l"(b));
}

// ============================================================================
// SCALAR kernel (R10-exact; measured best for L1/L3/L4).
// ============================================================================
template<int FIN, int H, int P, int KREG, int THREADS, bool FUSE_DENSE>
__global__ void __launch_bounds__(THREADS, 1)
rnn_layer(const float* __restrict__ x, const float* __restrict__ Wx,
          const float* __restrict__ Wh, const float* __restrict__ bias,
          float* __restrict__ hout, const float* __restrict__ Wd,
          const float* __restrict__ bd, float* __restrict__ out)
{
    constexpr int BT  = 4;
    constexpr int KV  = FIN + H;
    constexpr int KS  = KV / P;
    constexpr int KSM = KS - KREG;
    constexpr int CNT  = (BT * H + THREADS - 1) / THREADS;
    constexpr int CNTX = (BT * FIN + THREADS - 1) / THREADS;
    constexpr int REDN = FUSE_DENSE ? THREADS : 1;
    static_assert(H * P == THREADS, "thread count");
    static_assert(KV % P == 0 && KSM >= 0, "k partition");
    static_assert(!FUSE_DENSE || CNT == 1, "dense fusion assumes CNT==1");

    extern __shared__ float ws[];                       // [P][KSM][H]
    __shared__ __align__(16) float4 buf[2][KV];
    __shared__ float part[(P > 1 ? P : 1)][BT][(P > 1 ? H : 1)];
    __shared__ float red[REDN];

    const int tid = threadIdx.x;
    const int j   = tid % H;
    const int p   = tid / H;
    const int b0  = blockIdx.x * BT;
    const int k0  = p * KS;

    float w[KREG > 0 ? KREG : 1];
    #pragma unroll
    for (int q = 0; q < KREG; ++q) {
        int v = k0 + q;
        w[q] = (v < FIN) ? __ldg(&Wx[v * H + j]) : __ldg(&Wh[(v - FIN) * H + j]);
    }
    if (KSM > 0) {
        for (int idx = tid; idx < P * KSM * H; idx += THREADS) {
            int pp = idx / (KSM * H);
            int rem = idx % (KSM * H);
            int s = rem / H, jj = rem % H;
            int v = pp * KS + KREG + s;
            ws[idx] = (v < FIN) ? Wx[v * H + jj] : Wh[(v - FIN) * H + jj];
        }
    }
    for (int i = tid; i < H; i += THREADS) buf[0][FIN + i] = make_float4(0.f, 0.f, 0.f, 0.f);
    #pragma unroll
    for (int q = 0; q < CNTX; ++q) {
        int i = tid + q * THREADS;
        if (i < BT * FIN) {
            int r = i / FIN, k = i % FIN;
            ((float*)buf[0])[k * 4 + r] = __ldcg(&x[((b0 + r) * TT + 0) * FIN + k]);
        }
    }

    const float bjj = bias[j];
    float bj[CNT];
    #pragma unroll
    for (int q = 0; q < CNT; ++q) {
        int e = tid + q * THREADS;
        bj[q] = (e < BT * H) ? bias[e % H] : 0.f;
    }

    __syncthreads();

    float dacc = 0.f;
    int cb = 0;

    for (int t = 0; t < TT; ++t) {
        const int nb = cb ^ 1;

        float xst[CNTX];
        if (t + 1 < TT) {
            #pragma unroll
            for (int q = 0; q < CNTX; ++q) {
                int i = tid + q * THREADS;
                if (i < BT * FIN)
                    xst[q] = __ldcg(&x[((b0 + i / FIN) * TT + (t + 1)) * FIN + (i % FIN)]);
            }
        }

        float a0 = 0.f, a1 = 0.f, a2 = 0.f, a3 = 0.f;
        const float4* ub = buf[cb] + k0;

        #pragma unroll
        for (int q = 0; q < KREG; ++q) {
            float4 v = ub[q];
            a0 = fmaf(v.x, w[q], a0);
            a1 = fmaf(v.y, w[q], a1);
            a2 = fmaf(v.z, w[q], a2);
            a3 = fmaf(v.w, w[q], a3);
        }
        if (KSM > 0) {
            const float* wsp = ws + (p * KSM) * H + j;
            #pragma unroll 8
            for (int s = 0; s < KSM; ++s) {
                float4 v = ub[KREG + s];
                float wv = wsp[s * H];
                a0 = fmaf(v.x, wv, a0);
                a1 = fmaf(v.y, wv, a1);
                a2 = fmaf(v.z, wv, a2);
                a3 = fmaf(v.w, wv, a3);
            }
        }

        if (P == 1) {
            float4 hv;
            hv.x = fmaxf(a0 + bjj, 0.f);
            hv.y = fmaxf(a1 + bjj, 0.f);
            hv.z = fmaxf(a2 + bjj, 0.f);
            hv.w = fmaxf(a3 + bjj, 0.f);
            buf[nb][FIN + j] = hv;
            if (t + 1 < TT) {
                #pragma unroll
                for (int q = 0; q < CNTX; ++q) {
                    int i = tid + q * THREADS;
                    if (i < BT * FIN)
                        ((float*)buf[nb])[(i % FIN) * 4 + (i / FIN)] = xst[q];
                }
            }
            __stcg(&hout[((b0 + 0) * TT + t) * H + j], hv.x);
            __stcg(&hout[((b0 + 1) * TT + t) * H + j], hv.y);
            __stcg(&hout[((b0 + 2) * TT + t) * H + j], hv.z);
            __stcg(&hout[((b0 + 3) * TT + t) * H + j], hv.w);
            __syncthreads();
        } else {
            part[p][0][j] = a0;
            part[p][1][j] = a1;
            part[p][2][j] = a2;
            part[p][3][j] = a3;
            if (t + 1 < TT) {
                #pragma unroll
                for (int q = 0; q < CNTX; ++q) {
                    int i = tid + q * THREADS;
                    if (i < BT * FIN)
                        ((float*)buf[nb])[(i % FIN) * 4 + (i / FIN)] = xst[q];
                }
            }
            __syncthreads();
            #pragma unroll
            for (int q = 0; q < CNT; ++q) {
                int e = tid + q * THREADS;
                if (e < BT * H) {
                    int r = e / H, jj = e % H;
                    float s = bj[q];
                    #pragma unroll
                    for (int pp = 0; pp < P; ++pp) s += part[pp][r][jj];
                    s = fmaxf(s, 0.f);
                    ((float*)buf[nb])[(FIN + jj) * 4 + r] = s;
                    if (FUSE_DENSE) {
                        dacc = fmaf(s, __ldg(&Wd[t * H + jj]), dacc);
                    } else {
                        __stcg(&hout[((b0 + r) * TT + t) * H + jj], s);
                    }
                }
            }
            __syncthreads();
        }
        cb = nb;
    }

    if (FUSE_DENSE) {
        red[tid] = dacc;
        __syncthreads();
        if (tid < BT) {
            float s = bd[0];
            #pragma unroll 8
            for (int q = 0; q < H; ++q) s += red[tid * H + q];
            out[b0 + tid] = s;
        }
    }
}

// ============================================================================
// K-PAIR FFMA2 kernel for layer 2 (P==1, 256 thr). R15 structure +
//   (a) manual 2-deep software pipeline in the smem-weight quad loop
//       (guaranteed LDS->use distance >= one full quad of FFMA2s)
//   (b) float2 x prefetch/commit (layout is pair-packed already)
// ============================================================================
template<int FIN, int H, int KREGROWS, int THREADS>
__global__ void __launch_bounds__(THREADS, 1)
rnn_layer_kp(const float* __restrict__ x, const float* __restrict__ Wx,
             const float* __restrict__ Wh, const float* __restrict__ bias,
             float* __restrict__ hout)
{
    constexpr int BT   = 4;
    constexpr int KV   = FIN + H;          // 384
    constexpr int KSMR = KV - KREGROWS;    // smem rows (192)
    constexpr int NRQ  = KREGROWS / 4;     // reg quad-blocks (48)
    constexpr int NSQ  = KSMR / 4;         // smem quad-blocks (48)
    constexpr int NWP  = KREGROWS / 2;     // reg u64 weight pairs (96)
    constexpr int CNX2 = (BT * FIN / 2) / THREADS;  // float2 x elems/thread (2)
    static_assert(H == THREADS, "P==1: one thread per column");
    static_assert(KREGROWS % 4 == 0 && KSMR % 4 == 0 && FIN % 4 == 0, "quads");
    static_assert((BT * FIN / 2) % THREADS == 0, "float2 staging");

    extern __shared__ float4 wq[];                 // [NSQ][H]: (W4s..W4s+3) per col
    __shared__ __align__(16) float2 abuf[2][BT][KV / 2];   // (a_2q, a_2q+1) pairs

    const int tid = threadIdx.x;
    const int j   = tid;
    const int b0  = blockIdx.x * BT;

    // ---- one-time: reg weight pairs (rows 0..KREGROWS) ----
    u64 w[NWP];
    #pragma unroll
    for (int q = 0; q < NWP; ++q) {
        int k = 2 * q;
        float lo = (k     < FIN) ? __ldg(&Wx[k * H + j])       : __ldg(&Wh[(k - FIN) * H + j]);
        float hi = (k + 1 < FIN) ? __ldg(&Wx[(k + 1) * H + j]) : __ldg(&Wh[(k + 1 - FIN) * H + j]);
        float2 tpack = make_float2(lo, hi);
        w[q] = *(const u64*)&tpack;
    }
    // ---- one-time: smem weight quads (rows KREGROWS..KV) ----
    for (int idx = tid; idx < NSQ * H; idx += THREADS) {
        int s = idx / H, jj = idx % H;
        int v = KREGROWS + 4 * s;
        float w0 = (v     < FIN) ? Wx[v * H + jj]       : Wh[(v - FIN) * H + jj];
        float w1 = (v + 1 < FIN) ? Wx[(v + 1) * H + jj] : Wh[(v + 1 - FIN) * H + jj];
        float w2 = (v + 2 < FIN) ? Wx[(v + 2) * H + jj] : Wh[(v + 2 - FIN) * H + jj];
        float w3 = (v + 3 < FIN) ? Wx[(v + 3) * H + jj] : Wh[(v + 3 - FIN) * H + jj];
        wq[idx] = make_float4(w0, w1, w2, w3);
    }
    // h_0 = 0
    for (int i = tid; i < BT * H; i += THREADS) {
        int r = i / H, k = i % H;
        ((float*)abuf[0][r])[FIN + k] = 0.f;
    }
    // prime x(t=0): float2 elements (thread covers pairs 2*tid, 2*tid+1)
    #pragma unroll
    for (int q = 0; q < CNX2; ++q) {
        int e = tid + q * THREADS;          // float2 index in [0, BT*FIN/2)
        int r = (2 * e) / FIN, k = (2 * e) % FIN;
        float2 v = *(const float2*)&x[((b0 + r) * TT + 0) * FIN + k];
        abuf[0][r][k / 2] = v;
    }
    const float bjj = bias[j];

    __syncthreads();

    int cb = 0;

    for (int t = 0; t < TT; ++t) {
        const int nb = cb ^ 1;

        // prefetch x(t+1) as float2
        float2 xst[CNX2];
        if (t + 1 < TT) {
            #pragma unroll
            for (int q = 0; q < CNX2; ++q) {
                int e = tid + q * THREADS;
                int r = (2 * e) / FIN, k = (2 * e) % FIN;
                xst[q] = *(const float2*)&x[((b0 + r) * TT + (t + 1)) * FIN + k];
            }
        }

        u64 acc0 = 0, acc1 = 0, acc2 = 0, acc3 = 0;   // (even-k, odd-k) per row
        const ulonglong2* a0p = (const ulonglong2*)abuf[cb][0];
        const ulonglong2* a1p = (const ulonglong2*)abuf[cb][1];
        const ulonglong2* a2p = (const ulonglong2*)abuf[cb][2];
        const ulonglong2* a3p = (const ulonglong2*)abuf[cb][3];

        // reg-weight quad blocks: fully unrolled, ptxas schedules
        #pragma unroll
        for (int s = 0; s < NRQ; ++s) {
            ulonglong2 v0 = a0p[s];
            ulonglong2 v1 = a1p[s];
            ulonglong2 v2 = a2p[s];
            ulonglong2 v3 = a3p[s];
            ffma2(acc0, v0.x, w[2 * s]);
            ffma2(acc1, v1.x, w[2 * s]);
            ffma2(acc2, v2.x, w[2 * s]);
            ffma2(acc3, v3.x, w[2 * s]);
            ffma2(acc0, v0.y, w[2 * s + 1]);
            ffma2(acc1, v1.y, w[2 * s + 1]);
            ffma2(acc2, v2.y, w[2 * s + 1]);
            ffma2(acc3, v3.y, w[2 * s + 1]);
        }
        // smem-weight quad blocks: 2-deep software pipeline (load s+1 before
        // issuing s's FFMA2s -> LDS latency covered by a full quad of math)
        {
            const float4* wqp = wq + j;
            float4 wv = wqp[0];
            ulonglong2 v0 = a0p[NRQ], v1 = a1p[NRQ], v2 = a2p[NRQ], v3 = a3p[NRQ];
            #pragma unroll 8
            for (int s = 0; s < NSQ; ++s) {
                float4 wc = wv;
                ulonglong2 c0 = v0, c1 = v1, c2 = v2, c3 = v3;
                if (s + 1 < NSQ) {
                    wv = wqp[(s + 1) * H];
                    v0 = a0p[NRQ + s + 1];
                    v1 = a1p[NRQ + s + 1];
                    v2 = a2p[NRQ + s + 1];
                    v3 = a3p[NRQ + s + 1];
                }
                u64 wlo = *(const u64*)&wc.x;
                u64 whi = *(const u64*)&wc.z;
                ffma2(acc0, c0.x, wlo);
                ffma2(acc1, c1.x, wlo);
                ffma2(acc2, c2.x, wlo);
                ffma2(acc3, c3.x, wlo);
                ffma2(acc0, c0.y, whi);
                ffma2(acc1, c1.y, whi);
                ffma2(acc2, c2.y, whi);
                ffma2(acc3, c3.y, whi);
            }
        }

        // epilogue: fold (even,odd) lanes, bias, relu, state + output
        float2 f0 = *(float2*)&acc0;
        float2 f1 = *(float2*)&acc1;
        float2 f2 = *(float2*)&acc2;
        float2 f3 = *(float2*)&acc3;
        float h0  = fmaxf(f0.x + f0.y + bjj, 0.f);
        float h1  = fmaxf(f1.x + f1.y + bjj, 0.f);
        float h2v = fmaxf(f2.x + f2.y + bjj, 0.f);
        float h3v = fmaxf(f3.x + f3.y + bjj, 0.f);
        ((float*)abuf[nb][0])[FIN + j] = h0;
        ((float*)abuf[nb][1])[FIN + j] = h1;
        ((float*)abuf[nb][2])[FIN + j] = h2v;
        ((float*)abuf[nb][3])[FIN + j] = h3v;
        if (t + 1 < TT) {
            #pragma unroll
            for (int q = 0; q < CNX2; ++q) {
                int e = tid + q * THREADS;
                int r = (2 * e) / FIN, k = (2 * e) % FIN;
                abuf[nb][r][k / 2] = xst[q];
            }
        }
        __stcg(&hout[((b0 + 0) * TT + t) * H + j], h0);
        __stcg(&hout[((b0 + 1) * TT + t) * H + j], h1);
        __stcg(&hout[((b0 + 2) * TT + t) * H + j], h2v);
        __stcg(&hout[((b0 + 3) * TT + t) * H + j], h3v);
        __syncthreads();                  // ONE barrier per step
        cb = nb;
    }
}

extern "C" void kernel_launch(void* const* d_in, const int* in_sizes, int n_in,
                              void* d_out, int out_size)
{
    (void)in_sizes; (void)n_in; (void)out_size;

    const float* x   = (const float*)d_in[0];
    const float* Wx1 = (const float*)d_in[1];
    const float* Wh1 = (const float*)d_in[2];
    const float* b1  = (const float*)d_in[3];
    const float* Wx2 = (const float*)d_in[4];
    const float* Wh2 = (const float*)d_in[5];
    const float* b2  = (const float*)d_in[6];
    const float* Wx3 = (const float*)d_in[7];
    const float* Wh3 = (const float*)d_in[8];
    const float* b3  = (const float*)d_in[9];
    const float* Wx4 = (const float*)d_in[10];
    const float* Wh4 = (const float*)d_in[11];
    const float* b4  = (const float*)d_in[12];
    const float* Wd  = (const float*)d_in[13];
    const float* bd  = (const float*)d_in[14];
    float* out = (float*)d_out;

    float *bufA = nullptr, *bufB = nullptr;
    cudaGetSymbolAddress((void**)&bufA, g_bufA);
    cudaGetSymbolAddress((void**)&bufB, g_bufB);

    const dim3 grid(BB / 4);   // 128 CTAs

    // Dynamic smem:
    //   L2 (kp): 48 quads * 256 cols * 16B = 196608 B
    //   L3:      4*16*128*4                = 32768 B
    constexpr int DynL2 = 48 * 256 * 16;
    constexpr int DynL3 = 4 * 16 * 128 * 4;
    cudaFuncSetAttribute(rnn_layer_kp<128, 256, 192, 256>,
                         cudaFuncAttributeMaxDynamicSharedMemorySize, DynL2);
    cudaFuncSetAttribute(rnn_layer<256, 128, 4, 80, 512, false>,
                         cudaFuncAttributeMaxDynamicSharedMemorySize, DynL3);

    // L1: scalar, 512 thr, P=4, KS=48 all in regs (R10-exact)
    rnn_layer<64, 128, 4, 48, 512, false><<<grid, 512, 0>>>(
        x, Wx1, Wh1, b1, bufA, nullptr, nullptr, nullptr);
    // L2: k-pair FFMA2 + software pipeline, 256 thr, P=1
    rnn_layer_kp<128, 256, 192, 256><<<grid, 256, DynL2>>>(
        bufA, Wx2, Wh2, b2, bufB);
    // L3: scalar, 512 thr, P=4, 80 regs + 16 smem rows (R10-exact)
    rnn_layer<256, 128, 4, 80, 512, false><<<grid, 512, DynL3>>>(
        bufB, Wx3, Wh3, b3, bufA, nullptr, nullptr, nullptr);
    // L4: scalar, 256 thr, P=4, KS=48 all in regs, fused dense (R10-exact)
    rnn_layer<128, 64, 4, 48, 256, true><<<grid, 256, 0>>>(
        bufA, Wx4, Wh4, b4, nullptr, Wd, bd, out);
}